// round 9
// baseline (speedup 1.0000x reference)
#include <cuda_runtime.h>
#include <cstdint>

#define N_NODES 50000
#define N_EDGES 800000
#define DIM     128
#define SCAN_NB 196   // 196*256 = 50176 >= N_NODES
#define BPITCH  136   // u32 pitch for packed-bf16x2 W planes (conflict-free)

// ---------------- scratch (device globals; no allocation allowed) ----------------
__device__ float    g_xbuf[N_NODES * DIM];  // fp32 node features (gather source)
__device__ float    g_h   [N_NODES * DIM];  // predictor A output (fp32)
__device__ float    g_B   [N_NODES * DIM];  // predictor B output (fp32)
// bf16 hi/lo split planes, A-fragment word layout: [node][64] packed bf16x2
__device__ uint32_t g_p0h[N_NODES * 64];    // pair 0: aggr planes / final-x planes
__device__ uint32_t g_p0l[N_NODES * 64];
__device__ uint32_t g_p1h[N_NODES * 64];    // pair 1: hidden planes
__device__ uint32_t g_p1l[N_NODES * 64];
__device__ float2   g_sev[N_EDGES];         // {src_bits, edge_attr} sorted by dst
__device__ int2     g_sep[N_EDGES];         // {src, edge_id} sorted by dst
__device__ int      g_deg [N_NODES];
__device__ int      g_row [N_NODES + 1];
__device__ int      g_cur [N_NODES];
__device__ int      g_bsum[SCAN_NB];
__device__ int      g_is64;

__device__ __forceinline__ float* buf32(int id) {
    switch (id) {
        case 0:  return g_xbuf;
        case 1:  return g_h;
        default: return g_B;
    }
}
__device__ __forceinline__ const uint32_t* planeh(int id) { return id == 0 ? g_p0h : g_p1h; }
__device__ __forceinline__ const uint32_t* planel(int id) { return id == 0 ? g_p0l : g_p1l; }
__device__ __forceinline__ uint32_t* planehw(int id) { return id == 0 ? g_p0h : g_p1h; }
__device__ __forceinline__ uint32_t* planelw(int id) { return id == 0 ? g_p0l : g_p1l; }

// ---------------- bf16 helpers ----------------
__device__ __forceinline__ uint32_t packbf(float vhi, float vlo) {
    uint32_t r;
    asm("cvt.rn.bf16x2.f32 %0, %1, %2;" : "=r"(r) : "f"(vhi), "f"(vlo));
    return r;
}
__device__ __forceinline__ void mma_bf16(float* c, const uint32_t* a,
                                         const uint32_t* b) {
    asm("mma.sync.aligned.m16n8k16.row.col.f32.bf16.bf16.f32 "
        "{%0,%1,%2,%3},{%4,%5,%6,%7},{%8,%9},{%0,%1,%2,%3};"
        : "+f"(c[0]), "+f"(c[1]), "+f"(c[2]), "+f"(c[3])
        : "r"(a[0]), "r"(a[1]), "r"(a[2]), "r"(a[3]), "r"(b[0]), "r"(b[1]));
}
// split (v0 = lower k, v1 = upper k) into bf16x2 hi + residual-lo words
__device__ __forceinline__ void split2(float2 v, uint32_t& hi, uint32_t& lo) {
    hi = packbf(v.y, v.x);
    float h0 = __uint_as_float(hi << 16);
    float h1 = __uint_as_float(hi & 0xffff0000u);
    lo = packbf(v.y - h1, v.x - h0);
}

// ---------------- edge-index access (dtype-agnostic) ----------------
__device__ __forceinline__ int ei_src(const void* ei, int e) {
    return g_is64 ? (int)((const long long*)ei)[e] : ((const int*)ei)[e];
}
__device__ __forceinline__ int ei_dst(const void* ei, int e) {
    return g_is64 ? (int)((const long long*)ei)[N_EDGES + e]
                  : ((const int*)ei)[N_EDGES + e];
}

// ---------------- dtype detect + degree zero (fused) ----------------
__global__ void k_detect_zero(const void* ei) {
    int i = blockIdx.x * blockDim.x + threadIdx.x;
    if (i < N_NODES) g_deg[i] = 0;
    if (blockIdx.x == 0) {
        __shared__ int s;
        if (threadIdx.x == 0) s = 0;
        __syncthreads();
        if (threadIdx.x < 64) {
            const unsigned* w = (const unsigned*)ei;
            if (w[2 * threadIdx.x + 1] != 0u) atomicOr(&s, 1);
        }
        __syncthreads();
        if (threadIdx.x == 0) g_is64 = (s == 0) ? 1 : 0;
    }
}

// ---------------- CSR build ----------------
__global__ void k_hist(const void* ei) {
    int i = blockIdx.x * blockDim.x + threadIdx.x;
    if (i < N_EDGES) atomicAdd(&g_deg[ei_dst(ei, i)], 1);
}

__global__ void k_scanA() {
    __shared__ int s[256];
    int t = threadIdx.x;
    int idx = blockIdx.x * 256 + t;
    int v = (idx < N_NODES) ? g_deg[idx] : 0;
    s[t] = v;
    __syncthreads();
    #pragma unroll
    for (int off = 1; off < 256; off <<= 1) {
        int add = (t >= off) ? s[t - off] : 0;
        __syncthreads();
        s[t] += add;
        __syncthreads();
    }
    int incl = s[t];
    if (idx < N_NODES) g_row[idx] = incl - v;
    if (t == 255) g_bsum[blockIdx.x] = incl;
}

__global__ void k_scanB() {
    __shared__ int s[256];
    int t = threadIdx.x;
    int v = (t < SCAN_NB) ? g_bsum[t] : 0;
    s[t] = v;
    __syncthreads();
    #pragma unroll
    for (int off = 1; off < 256; off <<= 1) {
        int add = (t >= off) ? s[t - off] : 0;
        __syncthreads();
        s[t] += add;
        __syncthreads();
    }
    if (t < SCAN_NB) g_bsum[t] = s[t] - v;  // exclusive
}

__global__ void k_scanC() {
    int idx = blockIdx.x * 256 + threadIdx.x;
    if (idx < N_NODES) {
        int r = g_row[idx] + g_bsum[blockIdx.x];
        g_row[idx] = r;
        g_cur[idx] = r;
    }
    if (idx == 0) g_row[N_NODES] = N_EDGES;
}

__global__ void k_scatter(const void* ei, const float* __restrict__ ea) {
    int e = blockIdx.x * blockDim.x + threadIdx.x;
    if (e >= N_EDGES) return;
    int d = ei_dst(ei, e);
    int s = ei_src(ei, e);
    int pos = atomicAdd(&g_cur[d], 1);
    g_sev[pos] = make_float2(__int_as_float(s), ea[e]);
    g_sep[pos] = make_int2(s, e);
}

// ---------------- CSR aggregation -> split planes (pair 0) ----------------
// acc[n] = x[n] + sum relu(x[src]+a*We+be); warp per node; writes hi/lo planes
__global__ void __launch_bounds__(256)
k_aggr(const float* __restrict__ xext,
       const float* __restrict__ We, const float* __restrict__ be) {
    int gt   = blockIdx.x * blockDim.x + threadIdx.x;
    int node = gt >> 5;
    int lane = gt & 31;
    if (node >= N_NODES) return;

    const float* xin = xext ? xext : g_xbuf;

    float4 wv = ((const float4*)We)[lane];
    float4 bv = ((const float4*)be)[lane];
    const float4* xv = (const float4*)xin;

    float4 acc = xv[(size_t)node * 32 + lane];   // (1+eps)*x, eps=0
    int j   = g_row[node];
    int end = g_row[node + 1];

    for (; j + 1 < end; j += 2) {
        float2 v0 = g_sev[j], v1 = g_sev[j + 1];
        int   s0 = __float_as_int(v0.x), s1 = __float_as_int(v1.x);
        float a0 = v0.y,                 a1 = v1.y;
        float4 x0 = xv[(size_t)s0 * 32 + lane];
        float4 x1 = xv[(size_t)s1 * 32 + lane];
        acc.x += fmaxf(x0.x + fmaf(a0, wv.x, bv.x), 0.f)
               + fmaxf(x1.x + fmaf(a1, wv.x, bv.x), 0.f);
        acc.y += fmaxf(x0.y + fmaf(a0, wv.y, bv.y), 0.f)
               + fmaxf(x1.y + fmaf(a1, wv.y, bv.y), 0.f);
        acc.z += fmaxf(x0.z + fmaf(a0, wv.z, bv.z), 0.f)
               + fmaxf(x1.z + fmaf(a1, wv.z, bv.z), 0.f);
        acc.w += fmaxf(x0.w + fmaf(a0, wv.w, bv.w), 0.f)
               + fmaxf(x1.w + fmaf(a1, wv.w, bv.w), 0.f);
    }
    if (j < end) {
        float2 v0 = g_sev[j];
        int   s0 = __float_as_int(v0.x);
        float a0 = v0.y;
        float4 x0 = xv[(size_t)s0 * 32 + lane];
        acc.x += fmaxf(x0.x + fmaf(a0, wv.x, bv.x), 0.f);
        acc.y += fmaxf(x0.y + fmaf(a0, wv.y, bv.y), 0.f);
        acc.z += fmaxf(x0.z + fmaf(a0, wv.z, bv.z), 0.f);
        acc.w += fmaxf(x0.w + fmaf(a0, wv.w, bv.w), 0.f);
    }
    uint32_t h0, l0, h1, l1;
    split2(make_float2(acc.x, acc.y), h0, l0);
    split2(make_float2(acc.z, acc.w), h1, l1);
    *(uint2*)&g_p0h[(size_t)node * 64 + lane * 2] = make_uint2(h0, h1);
    *(uint2*)&g_p0l[(size_t)node * 64 + lane * 2] = make_uint2(l0, l1);
}

// ---------------- tensor-core GEMM, A from split planes, bf16x3 ----------------
// block: 128 rows x 128 cols, 256 threads (8 warps), warp tile 32x64
__global__ void __launch_bounds__(256, 2)
k_gemm_tc(int ipA, const float* __restrict__ W,
          const float* __restrict__ bias, int io32, int iop,
          int relu, int nrows) {
    extern __shared__ uint32_t sWp[];          // 2 * 64 * BPITCH u32
    uint32_t* sHi = sWp;
    uint32_t* sLo = sWp + 64 * BPITCH;
    for (int i = threadIdx.x; i < 64 * 128; i += 256) {
        int k2 = i >> 7, n = i & 127;
        float v0 = __ldg(W + (2 * k2)     * DIM + n);
        float v1 = __ldg(W + (2 * k2 + 1) * DIM + n);
        uint32_t hi, lo;
        split2(make_float2(v0, v1), hi, lo);
        sHi[k2 * BPITCH + n] = hi;
        sLo[k2 * BPITCH + n] = lo;
    }
    __syncthreads();

    const uint32_t* Ah = planeh(ipA);
    const uint32_t* Al = planel(ipA);

    int warp = threadIdx.x >> 5, lane = threadIdx.x & 31;
    int g   = lane >> 2;    // 0..7
    int tid = lane & 3;     // 0..3
    int mbase = blockIdx.x * 128 + (warp >> 1) * 32;
    int nbase = (warp & 1) * 64;

    float acc[2][8][4];
    #pragma unroll
    for (int mt = 0; mt < 2; mt++)
        #pragma unroll
        for (int nt = 0; nt < 8; nt++)
            #pragma unroll
            for (int i = 0; i < 4; i++) acc[mt][nt][i] = 0.f;

    int r0[2], r1[2];
    #pragma unroll
    for (int mt = 0; mt < 2; mt++) {
        int a = mbase + mt * 16 + g;
        r0[mt] = min(a, nrows - 1);
        r1[mt] = min(a + 8, nrows - 1);
    }

    #pragma unroll 1
    for (int c0 = 0; c0 < 128; c0 += 16) {
        int kw = (c0 >> 1) + tid;   // A-plane word index
        uint32_t ah[2][4], al[2][4];
        #pragma unroll
        for (int mt = 0; mt < 2; mt++) {
            const uint32_t* ph0 = Ah + (size_t)r0[mt] * 64 + kw;
            const uint32_t* ph1 = Ah + (size_t)r1[mt] * 64 + kw;
            const uint32_t* pl0 = Al + (size_t)r0[mt] * 64 + kw;
            const uint32_t* pl1 = Al + (size_t)r1[mt] * 64 + kw;
            ah[mt][0] = __ldg(ph0);     ah[mt][1] = __ldg(ph1);
            ah[mt][2] = __ldg(ph0 + 4); ah[mt][3] = __ldg(ph1 + 4);
            al[mt][0] = __ldg(pl0);     al[mt][1] = __ldg(pl1);
            al[mt][2] = __ldg(pl0 + 4); al[mt][3] = __ldg(pl1 + 4);
        }
        #pragma unroll
        for (int nh = 0; nh < 2; nh++) {
            uint32_t bh[4][2], bl[4][2];
            #pragma unroll
            for (int q = 0; q < 4; q++) {
                int col = nbase + (nh * 4 + q) * 8 + g;
                bh[q][0] = sHi[kw * BPITCH + col];         // kw == c0/2 + tid
                bh[q][1] = sHi[(kw + 4) * BPITCH + col];
                bl[q][0] = sLo[kw * BPITCH + col];
                bl[q][1] = sLo[(kw + 4) * BPITCH + col];
            }
            #pragma unroll
            for (int mt = 0; mt < 2; mt++)
                #pragma unroll
                for (int q = 0; q < 4; q++) {
                    float* c = acc[mt][nh * 4 + q];
                    mma_bf16(c, al[mt], bh[q]);   // Al*Wh
                    mma_bf16(c, ah[mt], bl[q]);   // Ah*Wl
                    mma_bf16(c, ah[mt], bh[q]);   // Ah*Wh
                }
        }
    }

    float*    o32 = (io32 >= 0) ? buf32(io32) : nullptr;
    uint32_t* oph = (iop >= 0) ? planehw(iop) : nullptr;
    uint32_t* opl = (iop >= 0) ? planelw(iop) : nullptr;

    #pragma unroll
    for (int mt = 0; mt < 2; mt++) {
        int ra = mbase + mt * 16 + g;
        int rb = ra + 8;
        #pragma unroll
        for (int nt = 0; nt < 8; nt++) {
            int c = nbase + nt * 8 + tid * 2;
            float b0 = bias ? __ldg(bias + c)     : 0.f;
            float b1 = bias ? __ldg(bias + c + 1) : 0.f;
            float v0 = acc[mt][nt][0] + b0, v1 = acc[mt][nt][1] + b1;
            float v2 = acc[mt][nt][2] + b0, v3 = acc[mt][nt][3] + b1;
            if (relu) {
                v0 = fmaxf(v0, 0.f); v1 = fmaxf(v1, 0.f);
                v2 = fmaxf(v2, 0.f); v3 = fmaxf(v3, 0.f);
            }
            if (ra < nrows) {
                if (o32) *(float2*)&o32[(size_t)ra * DIM + c] = make_float2(v0, v1);
                if (oph) {
                    uint32_t hi, lo;
                    split2(make_float2(v0, v1), hi, lo);
                    oph[(size_t)ra * 64 + (c >> 1)] = hi;
                    opl[(size_t)ra * 64 + (c >> 1)] = lo;
                }
            }
            if (rb < nrows) {
                if (o32) *(float2*)&o32[(size_t)rb * DIM + c] = make_float2(v2, v3);
                if (oph) {
                    uint32_t hi, lo;
                    split2(make_float2(v2, v3), hi, lo);
                    oph[(size_t)rb * 64 + (c >> 1)] = hi;
                    opl[(size_t)rb * 64 + (c >> 1)] = lo;
                }
            }
        }
    }
}

// ---------------- edge predictor, CSR order ----------------
// warp per node d: t = B[d] + bp1 (once); per edge gather A[src];
// p = relu(A[src]+t) . Wp2; shfl-reduce; out[eid] = p + bp2
__global__ void __launch_bounds__(256)
k_edge_pred_csr(const float* __restrict__ bp1,
                const float* __restrict__ Wp2,
                const float* __restrict__ bp2,
                float* __restrict__ out) {
    int gt   = blockIdx.x * blockDim.x + threadIdx.x;
    int node = gt >> 5;
    int lane = gt & 31;
    if (node >= N_NODES) return;

    float4 b1 = ((const float4*)bp1)[lane];
    float4 w2 = ((const float4*)Wp2)[lane];
    float  b2 = __ldg(bp2);

    float4 t = ((const float4*)(g_B + (size_t)node * DIM))[lane];
    t.x += b1.x; t.y += b1.y; t.z += b1.z; t.w += b1.w;

    const float4* av4 = (const float4*)g_h;
    int j   = g_row[node];
    int end = g_row[node + 1];

    for (; j + 1 < end; j += 2) {
        int2 p0i = g_sep[j], p1i = g_sep[j + 1];
        float4 a0 = av4[(size_t)p0i.x * 32 + lane];
        float4 a1 = av4[(size_t)p1i.x * 32 + lane];
        float p0 = 0.f, p1 = 0.f;
        p0 = fmaf(fmaxf(a0.x + t.x, 0.f), w2.x, p0);
        p0 = fmaf(fmaxf(a0.y + t.y, 0.f), w2.y, p0);
        p0 = fmaf(fmaxf(a0.z + t.z, 0.f), w2.z, p0);
        p0 = fmaf(fmaxf(a0.w + t.w, 0.f), w2.w, p0);
        p1 = fmaf(fmaxf(a1.x + t.x, 0.f), w2.x, p1);
        p1 = fmaf(fmaxf(a1.y + t.y, 0.f), w2.y, p1);
        p1 = fmaf(fmaxf(a1.z + t.z, 0.f), w2.z, p1);
        p1 = fmaf(fmaxf(a1.w + t.w, 0.f), w2.w, p1);
        #pragma unroll
        for (int o = 16; o > 0; o >>= 1) {
            p0 += __shfl_xor_sync(0xffffffffu, p0, o);
            p1 += __shfl_xor_sync(0xffffffffu, p1, o);
        }
        if (lane == 0) out[p0i.y] = p0 + b2;
        if (lane == 1) out[p1i.y] = p1 + b2;
    }
    if (j < end) {
        int2 p0i = g_sep[j];
        float4 a0 = av4[(size_t)p0i.x * 32 + lane];
        float p0 = 0.f;
        p0 = fmaf(fmaxf(a0.x + t.x, 0.f), w2.x, p0);
        p0 = fmaf(fmaxf(a0.y + t.y, 0.f), w2.y, p0);
        p0 = fmaf(fmaxf(a0.z + t.z, 0.f), w2.z, p0);
        p0 = fmaf(fmaxf(a0.w + t.w, 0.f), w2.w, p0);
        #pragma unroll
        for (int o = 16; o > 0; o >>= 1)
            p0 += __shfl_xor_sync(0xffffffffu, p0, o);
        if (lane == 0) out[p0i.y] = p0 + b2;
    }
}

// ---------------- launch ----------------
extern "C" void kernel_launch(void* const* d_in, const int* in_sizes, int n_in,
                              void* d_out, int out_size) {
    const float* x   = (const float*)d_in[0];
    const float* ea  = (const float*)d_in[1];
    const void*  ei  = d_in[2];
    const float* Wl1 = (const float*)d_in[3];
    const float* bl1 = (const float*)d_in[4];
    const float* Wl2 = (const float*)d_in[5];
    const float* bl2 = (const float*)d_in[6];
    const float* We  = (const float*)d_in[7];
    const float* be  = (const float*)d_in[8];
    const float* Wp1 = (const float*)d_in[9];
    const float* bp1 = (const float*)d_in[10];
    const float* Wp2 = (const float*)d_in[11];
    const float* bp2 = (const float*)d_in[12];
    float* out = (float*)d_out;

    const int GEMM_SMEM = 2 * 64 * BPITCH * (int)sizeof(uint32_t);  // 69632
    cudaFuncSetAttribute(k_gemm_tc, cudaFuncAttributeMaxDynamicSharedMemorySize,
                         GEMM_SMEM);

    const int GEMM_GRID = (N_NODES + 127) / 128;         // 391
    const int EDGE_GRID = (N_EDGES + 255) / 256;         // 3125
    const int NODE_GRID = (N_NODES + 255) / 256;         // 196
    const int AGGR_GRID = (N_NODES * 32 + 255) / 256;    // 6250

    // dtype detect + CSR build (once per call)
    k_detect_zero<<<NODE_GRID, 256>>>(ei);
    k_hist<<<EDGE_GRID, 256>>>(ei);
    k_scanA<<<SCAN_NB, 256>>>();
    k_scanB<<<1, 256>>>();
    k_scanC<<<SCAN_NB, 256>>>();
    k_scatter<<<EDGE_GRID, 256>>>(ei, ea);

    for (int l = 0; l < 3; l++) {
        // aggr planes (pair 0) = split(x + sum(msg))
        k_aggr<<<AGGR_GRID, 256>>>((l == 0) ? x : nullptr,
                                   We + l * DIM, be + l * DIM);
        // h planes (pair 1) = split(relu(aggr @ Wl1 + bl1))
        k_gemm_tc<<<GEMM_GRID, 256, GEMM_SMEM>>>(0, Wl1 + l * DIM * DIM,
                                                 bl1 + l * DIM, -1, 1, 1, N_NODES);
        // x = relu(h @ Wl2 + bl2):  l<2 -> fp32 x (for next gather);
        //                           l==2 -> planes pair 0 (for predictor GEMMs)
        k_gemm_tc<<<GEMM_GRID, 256, GEMM_SMEM>>>(1, Wl2 + l * DIM * DIM,
                                                 bl2 + l * DIM,
                                                 (l < 2) ? 0 : -1,
                                                 (l < 2) ? -1 : 0, 1, N_NODES);
    }

    // A = x @ Wp1[0:128] (g_h fp32),  B = x @ Wp1[128:256] (g_B fp32)
    k_gemm_tc<<<GEMM_GRID, 256, GEMM_SMEM>>>(0, Wp1, nullptr, 1, -1, 0, N_NODES);
    k_gemm_tc<<<GEMM_GRID, 256, GEMM_SMEM>>>(0, Wp1 + DIM * DIM, nullptr, 2, -1, 0, N_NODES);

    k_edge_pred_csr<<<AGGR_GRID, 256>>>(bp1, Wp2, bp2, out);
}

// round 10
// speedup vs baseline: 1.0123x; 1.0123x over previous
#include <cuda_runtime.h>
#include <cstdint>

#define N_NODES 50000
#define N_EDGES 800000
#define DIM     128
#define SCAN_NB 196   // 196*256 = 50176 >= N_NODES
#define BPITCH  136   // u32 pitch for W planes (conflict-free LDS.32)
#define M_BLK   256   // GEMM rows per block
#define APITCH  68    // u32 pitch for A planes (conflict-free ldmatrix)

// ---------------- scratch (device globals; no allocation allowed) ----------------
__device__ float  g_xbuf[N_NODES * DIM];   // current node features
__device__ float  g_h   [N_NODES * DIM];   // hidden / predictor A
__device__ float  g_aggr[N_NODES * DIM];   // x + message aggregation
__device__ float  g_B   [N_NODES * DIM];   // predictor B
__device__ float2 g_sev [N_EDGES];         // {src_bits, edge_attr} sorted by dst
__device__ int2   g_sep [N_EDGES];         // {src, edge_id} sorted by dst
__device__ int    g_deg [N_NODES];
__device__ int    g_row [N_NODES + 1];
__device__ int    g_cur [N_NODES];
__device__ int    g_bsum[SCAN_NB];
__device__ int    g_is64;

__device__ __forceinline__ float* bufptr(int id) {
    switch (id) {
        case 0:  return g_xbuf;
        case 1:  return g_h;
        case 2:  return g_aggr;
        default: return g_B;
    }
}

// ---------------- bf16 / mma helpers ----------------
__device__ __forceinline__ uint32_t packbf(float vhi, float vlo) {
    uint32_t r;
    asm("cvt.rn.bf16x2.f32 %0, %1, %2;" : "=r"(r) : "f"(vhi), "f"(vlo));
    return r;
}
__device__ __forceinline__ void mma_bf16(float* c, const uint32_t* a,
                                         const uint32_t* b) {
    asm("mma.sync.aligned.m16n8k16.row.col.f32.bf16.bf16.f32 "
        "{%0,%1,%2,%3},{%4,%5,%6,%7},{%8,%9},{%0,%1,%2,%3};"
        : "+f"(c[0]), "+f"(c[1]), "+f"(c[2]), "+f"(c[3])
        : "r"(a[0]), "r"(a[1]), "r"(a[2]), "r"(a[3]), "r"(b[0]), "r"(b[1]));
}
// split (v.x = lower k, v.y = upper k) into bf16x2 hi + residual-lo words
__device__ __forceinline__ void split2(float2 v, uint32_t& hi, uint32_t& lo) {
    hi = packbf(v.y, v.x);
    float h0 = __uint_as_float(hi << 16);
    float h1 = __uint_as_float(hi & 0xffff0000u);
    lo = packbf(v.y - h1, v.x - h0);
}
__device__ __forceinline__ void ldsm4(uint32_t* r, uint32_t addr) {
    asm volatile("ldmatrix.sync.aligned.m8n8.x4.shared.b16 {%0,%1,%2,%3}, [%4];"
        : "=r"(r[0]), "=r"(r[1]), "=r"(r[2]), "=r"(r[3]) : "r"(addr));
}
__device__ __forceinline__ uint32_t smem_u32(const void* p) {
    return (uint32_t)__cvta_generic_to_shared(p);
}

// ---------------- edge-index access (dtype-agnostic) ----------------
__device__ __forceinline__ int ei_src(const void* ei, int e) {
    return g_is64 ? (int)((const long long*)ei)[e] : ((const int*)ei)[e];
}
__device__ __forceinline__ int ei_dst(const void* ei, int e) {
    return g_is64 ? (int)((const long long*)ei)[N_EDGES + e]
                  : ((const int*)ei)[N_EDGES + e];
}

// ---------------- dtype detect + degree zero (fused) ----------------
__global__ void k_detect_zero(const void* ei) {
    int i = blockIdx.x * blockDim.x + threadIdx.x;
    if (i < N_NODES) g_deg[i] = 0;
    if (blockIdx.x == 0) {
        __shared__ int s;
        if (threadIdx.x == 0) s = 0;
        __syncthreads();
        if (threadIdx.x < 64) {
            const unsigned* w = (const unsigned*)ei;
            if (w[2 * threadIdx.x + 1] != 0u) atomicOr(&s, 1);
        }
        __syncthreads();
        if (threadIdx.x == 0) g_is64 = (s == 0) ? 1 : 0;
    }
}

// ---------------- CSR build ----------------
__global__ void k_hist(const void* ei) {
    int i = blockIdx.x * blockDim.x + threadIdx.x;
    if (i < N_EDGES) atomicAdd(&g_deg[ei_dst(ei, i)], 1);
}

__global__ void k_scanA() {
    __shared__ int s[256];
    int t = threadIdx.x;
    int idx = blockIdx.x * 256 + t;
    int v = (idx < N_NODES) ? g_deg[idx] : 0;
    s[t] = v;
    __syncthreads();
    #pragma unroll
    for (int off = 1; off < 256; off <<= 1) {
        int add = (t >= off) ? s[t - off] : 0;
        __syncthreads();
        s[t] += add;
        __syncthreads();
    }
    int incl = s[t];
    if (idx < N_NODES) g_row[idx] = incl - v;
    if (t == 255) g_bsum[blockIdx.x] = incl;
}

__global__ void k_scanB() {
    __shared__ int s[256];
    int t = threadIdx.x;
    int v = (t < SCAN_NB) ? g_bsum[t] : 0;
    s[t] = v;
    __syncthreads();
    #pragma unroll
    for (int off = 1; off < 256; off <<= 1) {
        int add = (t >= off) ? s[t - off] : 0;
        __syncthreads();
        s[t] += add;
        __syncthreads();
    }
    if (t < SCAN_NB) g_bsum[t] = s[t] - v;  // exclusive
}

__global__ void k_scanC() {
    int idx = blockIdx.x * 256 + threadIdx.x;
    if (idx < N_NODES) {
        int r = g_row[idx] + g_bsum[blockIdx.x];
        g_row[idx] = r;
        g_cur[idx] = r;
    }
    if (idx == 0) g_row[N_NODES] = N_EDGES;
}

__global__ void k_scatter(const void* ei, const float* __restrict__ ea) {
    int e = blockIdx.x * blockDim.x + threadIdx.x;
    if (e >= N_EDGES) return;
    int d = ei_dst(ei, e);
    int s = ei_src(ei, e);
    int pos = atomicAdd(&g_cur[d], 1);
    g_sev[pos] = make_float2(__int_as_float(s), ea[e]);
    g_sep[pos] = make_int2(s, e);
}

// ---------------- CSR aggregation (fp32 out, as R8) ----------------
__global__ void __launch_bounds__(256)
k_aggr(const float* __restrict__ xext,
       const float* __restrict__ We, const float* __restrict__ be) {
    int gt   = blockIdx.x * blockDim.x + threadIdx.x;
    int node = gt >> 5;
    int lane = gt & 31;
    if (node >= N_NODES) return;

    const float* xin = xext ? xext : g_xbuf;

    float4 wv = ((const float4*)We)[lane];
    float4 bv = ((const float4*)be)[lane];
    const float4* xv = (const float4*)xin;

    float4 acc = xv[(size_t)node * 32 + lane];   // (1+eps)*x, eps=0
    int j   = g_row[node];
    int end = g_row[node + 1];

    for (; j + 3 < end; j += 4) {
        float2 v0 = g_sev[j],     v1 = g_sev[j + 1];
        float2 v2 = g_sev[j + 2], v3 = g_sev[j + 3];
        int s0 = __float_as_int(v0.x), s1 = __float_as_int(v1.x);
        int s2 = __float_as_int(v2.x), s3 = __float_as_int(v3.x);
        float4 x0 = xv[(size_t)s0 * 32 + lane];
        float4 x1 = xv[(size_t)s1 * 32 + lane];
        float4 x2 = xv[(size_t)s2 * 32 + lane];
        float4 x3 = xv[(size_t)s3 * 32 + lane];
        acc.x += fmaxf(x0.x + fmaf(v0.y, wv.x, bv.x), 0.f)
               + fmaxf(x1.x + fmaf(v1.y, wv.x, bv.x), 0.f)
               + fmaxf(x2.x + fmaf(v2.y, wv.x, bv.x), 0.f)
               + fmaxf(x3.x + fmaf(v3.y, wv.x, bv.x), 0.f);
        acc.y += fmaxf(x0.y + fmaf(v0.y, wv.y, bv.y), 0.f)
               + fmaxf(x1.y + fmaf(v1.y, wv.y, bv.y), 0.f)
               + fmaxf(x2.y + fmaf(v2.y, wv.y, bv.y), 0.f)
               + fmaxf(x3.y + fmaf(v3.y, wv.y, bv.y), 0.f);
        acc.z += fmaxf(x0.z + fmaf(v0.y, wv.z, bv.z), 0.f)
               + fmaxf(x1.z + fmaf(v1.y, wv.z, bv.z), 0.f)
               + fmaxf(x2.z + fmaf(v2.y, wv.z, bv.z), 0.f)
               + fmaxf(x3.z + fmaf(v3.y, wv.z, bv.z), 0.f);
        acc.w += fmaxf(x0.w + fmaf(v0.y, wv.w, bv.w), 0.f)
               + fmaxf(x1.w + fmaf(v1.y, wv.w, bv.w), 0.f)
               + fmaxf(x2.w + fmaf(v2.y, wv.w, bv.w), 0.f)
               + fmaxf(x3.w + fmaf(v3.y, wv.w, bv.w), 0.f);
    }
    for (; j < end; j++) {
        float2 v0 = g_sev[j];
        int s0 = __float_as_int(v0.x);
        float4 x0 = xv[(size_t)s0 * 32 + lane];
        acc.x += fmaxf(x0.x + fmaf(v0.y, wv.x, bv.x), 0.f);
        acc.y += fmaxf(x0.y + fmaf(v0.y, wv.y, bv.y), 0.f);
        acc.z += fmaxf(x0.z + fmaf(v0.y, wv.z, bv.z), 0.f);
        acc.w += fmaxf(x0.w + fmaf(v0.y, wv.w, bv.w), 0.f);
    }
    ((float4*)g_aggr)[(size_t)node * 32 + lane] = acc;
}

// ---------------- tensor-core GEMM: out = act(A @ W + bias), bf16x3 ----------------
// block: 256 rows x 128 cols, 512 threads (16 warps), warp tile 32x64
// A staged in smem as bf16 hi/lo planes, fragments via ldmatrix.x4
__global__ void __launch_bounds__(512, 1)
k_gemm_tc(int ia, const float* __restrict__ W,
          const float* __restrict__ bias, int io, int relu, int nrows) {
    extern __shared__ uint32_t smem[];
    uint32_t* sAh = smem;                        // M_BLK*APITCH
    uint32_t* sAl = smem + M_BLK * APITCH;
    uint32_t* sHi = smem + 2 * M_BLK * APITCH;   // 64*BPITCH
    uint32_t* sLo = sHi + 64 * BPITCH;

    const float* A   = bufptr(ia);
    float*       out = bufptr(io);

    // stage W planes
    for (int i = threadIdx.x; i < 64 * 128; i += 512) {
        int k2 = i >> 7, n = i & 127;
        float v0 = __ldg(W + (2 * k2)     * DIM + n);
        float v1 = __ldg(W + (2 * k2 + 1) * DIM + n);
        uint32_t hi, lo;
        split2(make_float2(v0, v1), hi, lo);
        sHi[k2 * BPITCH + n] = hi;
        sLo[k2 * BPITCH + n] = lo;
    }
    // stage A planes (coalesced float2 loads, split once)
    int rowbase = blockIdx.x * M_BLK;
    for (int i = threadIdx.x; i < M_BLK * 64; i += 512) {
        int r = i >> 6, w = i & 63;
        int gr = min(rowbase + r, nrows - 1);
        float2 v = *(const float2*)(A + (size_t)gr * DIM + w * 2);
        uint32_t hi, lo;
        split2(v, hi, lo);
        sAh[r * APITCH + w] = hi;
        sAl[r * APITCH + w] = lo;
    }
    __syncthreads();

    int warp = threadIdx.x >> 5, lane = threadIdx.x & 31;
    int g   = lane >> 2;    // 0..7
    int tid = lane & 3;     // 0..3
    int lmbase = (warp >> 1) * 32;     // warp's local row base (0..224)
    int nbase  = (warp & 1) * 64;

    // ldmatrix lane mapping: quads 0/1 -> k-lo rows r/r+8, quads 2/3 -> k-hi
    int lm_r  = ((lane >> 3) & 1) * 8 + (lane & 7);
    int lm_k4 = (lane >> 4) * 4;       // 0 or 4 words

    uint32_t sAh_base = smem_u32(sAh);
    uint32_t sAl_base = smem_u32(sAl);

    float acc[2][8][4];
    #pragma unroll
    for (int mt = 0; mt < 2; mt++)
        #pragma unroll
        for (int nt = 0; nt < 8; nt++)
            #pragma unroll
            for (int i = 0; i < 4; i++) acc[mt][nt][i] = 0.f;

    #pragma unroll 1
    for (int c0 = 0; c0 < 128; c0 += 16) {
        int kw = c0 >> 1;
        uint32_t ah[2][4], al[2][4];
        #pragma unroll
        for (int mt = 0; mt < 2; mt++) {
            uint32_t off = ((lmbase + mt * 16 + lm_r) * APITCH + kw + lm_k4) * 4;
            ldsm4(ah[mt], sAh_base + off);
            ldsm4(al[mt], sAl_base + off);
        }
        int kb = kw + tid;
        #pragma unroll
        for (int nh = 0; nh < 2; nh++) {
            uint32_t bh[4][2], bl[4][2];
            #pragma unroll
            for (int q = 0; q < 4; q++) {
                int col = nbase + (nh * 4 + q) * 8 + g;
                bh[q][0] = sHi[kb * BPITCH + col];
                bh[q][1] = sHi[(kb + 4) * BPITCH + col];
                bl[q][0] = sLo[kb * BPITCH + col];
                bl[q][1] = sLo[(kb + 4) * BPITCH + col];
            }
            #pragma unroll
            for (int mt = 0; mt < 2; mt++)
                #pragma unroll
                for (int q = 0; q < 4; q++) {
                    float* c = acc[mt][nh * 4 + q];
                    mma_bf16(c, al[mt], bh[q]);   // Al*Wh
                    mma_bf16(c, ah[mt], bl[q]);   // Ah*Wl
                    mma_bf16(c, ah[mt], bh[q]);   // Ah*Wh
                }
        }
    }

    #pragma unroll
    for (int mt = 0; mt < 2; mt++) {
        int ra = rowbase + lmbase + mt * 16 + g;
        int rb = ra + 8;
        #pragma unroll
        for (int nt = 0; nt < 8; nt++) {
            int c = nbase + nt * 8 + tid * 2;
            float b0 = bias ? __ldg(bias + c)     : 0.f;
            float b1 = bias ? __ldg(bias + c + 1) : 0.f;
            float v0 = acc[mt][nt][0] + b0, v1 = acc[mt][nt][1] + b1;
            float v2 = acc[mt][nt][2] + b0, v3 = acc[mt][nt][3] + b1;
            if (relu) {
                v0 = fmaxf(v0, 0.f); v1 = fmaxf(v1, 0.f);
                v2 = fmaxf(v2, 0.f); v3 = fmaxf(v3, 0.f);
            }
            if (ra < nrows) *(float2*)&out[(size_t)ra * DIM + c] = make_float2(v0, v1);
            if (rb < nrows) *(float2*)&out[(size_t)rb * DIM + c] = make_float2(v2, v3);
        }
    }
}

// ---------------- edge predictor, CSR order ----------------
__global__ void __launch_bounds__(256)
k_edge_pred_csr(const float* __restrict__ bp1,
                const float* __restrict__ Wp2,
                const float* __restrict__ bp2,
                float* __restrict__ out) {
    int gt   = blockIdx.x * blockDim.x + threadIdx.x;
    int node = gt >> 5;
    int lane = gt & 31;
    if (node >= N_NODES) return;

    float4 b1 = ((const float4*)bp1)[lane];
    float4 w2 = ((const float4*)Wp2)[lane];
    float  b2 = __ldg(bp2);

    float4 t = ((const float4*)(g_B + (size_t)node * DIM))[lane];
    t.x += b1.x; t.y += b1.y; t.z += b1.z; t.w += b1.w;

    const float4* av4 = (const float4*)g_h;
    int j   = g_row[node];
    int end = g_row[node + 1];

    for (; j + 1 < end; j += 2) {
        int2 p0i = g_sep[j], p1i = g_sep[j + 1];
        float4 a0 = av4[(size_t)p0i.x * 32 + lane];
        float4 a1 = av4[(size_t)p1i.x * 32 + lane];
        float p0 = 0.f, p1 = 0.f;
        p0 = fmaf(fmaxf(a0.x + t.x, 0.f), w2.x, p0);
        p0 = fmaf(fmaxf(a0.y + t.y, 0.f), w2.y, p0);
        p0 = fmaf(fmaxf(a0.z + t.z, 0.f), w2.z, p0);
        p0 = fmaf(fmaxf(a0.w + t.w, 0.f), w2.w, p0);
        p1 = fmaf(fmaxf(a1.x + t.x, 0.f), w2.x, p1);
        p1 = fmaf(fmaxf(a1.y + t.y, 0.f), w2.y, p1);
        p1 = fmaf(fmaxf(a1.z + t.z, 0.f), w2.z, p1);
        p1 = fmaf(fmaxf(a1.w + t.w, 0.f), w2.w, p1);
        #pragma unroll
        for (int o = 16; o > 0; o >>= 1) {
            p0 += __shfl_xor_sync(0xffffffffu, p0, o);
            p1 += __shfl_xor_sync(0xffffffffu, p1, o);
        }
        if (lane == 0) out[p0i.y] = p0 + b2;
        if (lane == 1) out[p1i.y] = p1 + b2;
    }
    if (j < end) {
        int2 p0i = g_sep[j];
        float4 a0 = av4[(size_t)p0i.x * 32 + lane];
        float p0 = 0.f;
        p0 = fmaf(fmaxf(a0.x + t.x, 0.f), w2.x, p0);
        p0 = fmaf(fmaxf(a0.y + t.y, 0.f), w2.y, p0);
        p0 = fmaf(fmaxf(a0.z + t.z, 0.f), w2.z, p0);
        p0 = fmaf(fmaxf(a0.w + t.w, 0.f), w2.w, p0);
        #pragma unroll
        for (int o = 16; o > 0; o >>= 1)
            p0 += __shfl_xor_sync(0xffffffffu, p0, o);
        if (lane == 0) out[p0i.y] = p0 + b2;
    }
}

// ---------------- launch ----------------
extern "C" void kernel_launch(void* const* d_in, const int* in_sizes, int n_in,
                              void* d_out, int out_size) {
    const float* x   = (const float*)d_in[0];
    const float* ea  = (const float*)d_in[1];
    const void*  ei  = d_in[2];
    const float* Wl1 = (const float*)d_in[3];
    const float* bl1 = (const float*)d_in[4];
    const float* Wl2 = (const float*)d_in[5];
    const float* bl2 = (const float*)d_in[6];
    const float* We  = (const float*)d_in[7];
    const float* be  = (const float*)d_in[8];
    const float* Wp1 = (const float*)d_in[9];
    const float* bp1 = (const float*)d_in[10];
    const float* Wp2 = (const float*)d_in[11];
    const float* bp2 = (const float*)d_in[12];
    float* out = (float*)d_out;

    const int GEMM_SMEM = (2 * M_BLK * APITCH + 2 * 64 * BPITCH) * (int)sizeof(uint32_t);
    cudaFuncSetAttribute(k_gemm_tc, cudaFuncAttributeMaxDynamicSharedMemorySize,
                         GEMM_SMEM);

    const int GEMM_GRID = (N_NODES + M_BLK - 1) / M_BLK;   // 196
    const int EDGE_GRID = (N_EDGES + 255) / 256;           // 3125
    const int NODE_GRID = (N_NODES + 255) / 256;           // 196
    const int AGGR_GRID = (N_NODES * 32 + 255) / 256;      // 6250

    // dtype detect + CSR build (once per call)
    k_detect_zero<<<NODE_GRID, 256>>>(ei);
    k_hist<<<EDGE_GRID, 256>>>(ei);
    k_scanA<<<SCAN_NB, 256>>>();
    k_scanB<<<1, 256>>>();
    k_scanC<<<SCAN_NB, 256>>>();
    k_scatter<<<EDGE_GRID, 256>>>(ei, ea);

    for (int l = 0; l < 3; l++) {
        // aggr = x + sum(msg);  layer 0 reads the external x directly
        k_aggr<<<AGGR_GRID, 256>>>((l == 0) ? x : nullptr,
                                   We + l * DIM, be + l * DIM);
        // h = relu(aggr @ Wl1 + bl1)
        k_gemm_tc<<<GEMM_GRID, 512, GEMM_SMEM>>>(2, Wl1 + l * DIM * DIM,
                                                 bl1 + l * DIM, 1, 1, N_NODES);
        // x = relu(h @ Wl2 + bl2)
        k_gemm_tc<<<GEMM_GRID, 512, GEMM_SMEM>>>(1, Wl2 + l * DIM * DIM,
                                                 bl2 + l * DIM, 0, 1, N_NODES);
    }

    // A = x @ Wp1[0:128] (g_h),  B = x @ Wp1[128:256] (g_B)
    k_gemm_tc<<<GEMM_GRID, 512, GEMM_SMEM>>>(0, Wp1, nullptr, 1, 0, N_NODES);
    k_gemm_tc<<<GEMM_GRID, 512, GEMM_SMEM>>>(0, Wp1 + DIM * DIM, nullptr, 3, 0, N_NODES);

    k_edge_pred_csr<<<AGGR_GRID, 256>>>(bp1, Wp2, bp2, out);
}

// round 11
// speedup vs baseline: 1.2237x; 1.2088x over previous
#include <cuda_runtime.h>
#include <cstdint>

#define N_NODES 50000
#define N_EDGES 800000
#define DIM     128
#define SCAN_NB 196   // 196*256 = 50176 >= N_NODES
#define BPITCH  136   // u32 pitch for packed-bf16x2 W planes (conflict-free)

// ---------------- scratch (device globals; no allocation allowed) ----------------
__device__ float  g_xbuf[N_NODES * DIM];   // current node features
__device__ float  g_h   [N_NODES * DIM];   // hidden / predictor A
__device__ float  g_aggr[N_NODES * DIM];   // x + message aggregation
__device__ float  g_B   [N_NODES * DIM];   // predictor B
__device__ float2 g_sev [N_EDGES];         // {src_bits, edge_attr} sorted by dst
__device__ int2   g_sep [N_EDGES];         // {src, edge_id} sorted by dst
__device__ int    g_deg [N_NODES];
__device__ int    g_row [N_NODES + 1];
__device__ int    g_cur [N_NODES];
__device__ int    g_bsum[SCAN_NB];
__device__ int    g_is64;

__device__ __forceinline__ float* bufptr(int id) {
    switch (id) {
        case 0:  return g_xbuf;
        case 1:  return g_h;
        case 2:  return g_aggr;
        default: return g_B;
    }
}

// ---------------- bf16 / mma helpers ----------------
__device__ __forceinline__ uint32_t packbf(float vhi, float vlo) {
    uint32_t r;
    asm("cvt.rn.bf16x2.f32 %0, %1, %2;" : "=r"(r) : "f"(vhi), "f"(vlo));
    return r;
}
__device__ __forceinline__ void mma_bf16(float* c, const uint32_t* a,
                                         const uint32_t* b) {
    asm("mma.sync.aligned.m16n8k16.row.col.f32.bf16.bf16.f32 "
        "{%0,%1,%2,%3},{%4,%5,%6,%7},{%8,%9},{%0,%1,%2,%3};"
        : "+f"(c[0]), "+f"(c[1]), "+f"(c[2]), "+f"(c[3])
        : "r"(a[0]), "r"(a[1]), "r"(a[2]), "r"(a[3]), "r"(b[0]), "r"(b[1]));
}
// split (v.x = lower k, v.y = upper k) into bf16x2 hi + residual-lo words
__device__ __forceinline__ void split2(float2 v, uint32_t& hi, uint32_t& lo) {
    hi = packbf(v.y, v.x);
    float h0 = __uint_as_float(hi << 16);
    float h1 = __uint_as_float(hi & 0xffff0000u);
    lo = packbf(v.y - h1, v.x - h0);
}

// ---------------- edge-index access (dtype-agnostic) ----------------
__device__ __forceinline__ int ei_src(const void* ei, int e) {
    return g_is64 ? (int)((const long long*)ei)[e] : ((const int*)ei)[e];
}
__device__ __forceinline__ int ei_dst(const void* ei, int e) {
    return g_is64 ? (int)((const long long*)ei)[N_EDGES + e]
                  : ((const int*)ei)[N_EDGES + e];
}

// ---------------- dtype detect + degree zero (fused) ----------------
__global__ void k_detect_zero(const void* ei) {
    int i = blockIdx.x * blockDim.x + threadIdx.x;
    if (i < N_NODES) g_deg[i] = 0;
    if (blockIdx.x == 0) {
        __shared__ int s;
        if (threadIdx.x == 0) s = 0;
        __syncthreads();
        if (threadIdx.x < 64) {
            const unsigned* w = (const unsigned*)ei;
            if (w[2 * threadIdx.x + 1] != 0u) atomicOr(&s, 1);
        }
        __syncthreads();
        if (threadIdx.x == 0) g_is64 = (s == 0) ? 1 : 0;
    }
}

// ---------------- CSR build ----------------
__global__ void k_hist(const void* ei) {
    int i = blockIdx.x * blockDim.x + threadIdx.x;
    if (i < N_EDGES) atomicAdd(&g_deg[ei_dst(ei, i)], 1);
}

__global__ void k_scanA() {
    __shared__ int s[256];
    int t = threadIdx.x;
    int idx = blockIdx.x * 256 + t;
    int v = (idx < N_NODES) ? g_deg[idx] : 0;
    s[t] = v;
    __syncthreads();
    #pragma unroll
    for (int off = 1; off < 256; off <<= 1) {
        int add = (t >= off) ? s[t - off] : 0;
        __syncthreads();
        s[t] += add;
        __syncthreads();
    }
    int incl = s[t];
    if (idx < N_NODES) g_row[idx] = incl - v;
    if (t == 255) g_bsum[blockIdx.x] = incl;
}

__global__ void k_scanB() {
    __shared__ int s[256];
    int t = threadIdx.x;
    int v = (t < SCAN_NB) ? g_bsum[t] : 0;
    s[t] = v;
    __syncthreads();
    #pragma unroll
    for (int off = 1; off < 256; off <<= 1) {
        int add = (t >= off) ? s[t - off] : 0;
        __syncthreads();
        s[t] += add;
        __syncthreads();
    }
    if (t < SCAN_NB) g_bsum[t] = s[t] - v;  // exclusive
}

__global__ void k_scanC() {
    int idx = blockIdx.x * 256 + threadIdx.x;
    if (idx < N_NODES) {
        int r = g_row[idx] + g_bsum[blockIdx.x];
        g_row[idx] = r;
        g_cur[idx] = r;
    }
    if (idx == 0) g_row[N_NODES] = N_EDGES;
}

__global__ void k_scatter(const void* ei, const float* __restrict__ ea) {
    int e = blockIdx.x * blockDim.x + threadIdx.x;
    if (e >= N_EDGES) return;
    int d = ei_dst(ei, e);
    int s = ei_src(ei, e);
    int pos = atomicAdd(&g_cur[d], 1);
    g_sev[pos] = make_float2(__int_as_float(s), ea[e]);
    g_sep[pos] = make_int2(s, e);
}

// ---------------- CSR aggregation ----------------
// aggr[n] = x[n] + sum_{e in row n} relu(x[src_e] + a_e*We + be); warp per node
__global__ void __launch_bounds__(256)
k_aggr(const float* __restrict__ xext,
       const float* __restrict__ We, const float* __restrict__ be) {
    int gt   = blockIdx.x * blockDim.x + threadIdx.x;
    int node = gt >> 5;
    int lane = gt & 31;
    if (node >= N_NODES) return;

    const float* xin = xext ? xext : g_xbuf;

    float4 wv = ((const float4*)We)[lane];
    float4 bv = ((const float4*)be)[lane];
    const float4* xv = (const float4*)xin;

    float4 acc = xv[(size_t)node * 32 + lane];   // (1+eps)*x, eps=0
    int j   = g_row[node];
    int end = g_row[node + 1];

    for (; j + 3 < end; j += 4) {
        float2 v0 = g_sev[j],     v1 = g_sev[j + 1];
        float2 v2 = g_sev[j + 2], v3 = g_sev[j + 3];
        int s0 = __float_as_int(v0.x), s1 = __float_as_int(v1.x);
        int s2 = __float_as_int(v2.x), s3 = __float_as_int(v3.x);
        float4 x0 = xv[(size_t)s0 * 32 + lane];
        float4 x1 = xv[(size_t)s1 * 32 + lane];
        float4 x2 = xv[(size_t)s2 * 32 + lane];
        float4 x3 = xv[(size_t)s3 * 32 + lane];
        acc.x += fmaxf(x0.x + fmaf(v0.y, wv.x, bv.x), 0.f)
               + fmaxf(x1.x + fmaf(v1.y, wv.x, bv.x), 0.f)
               + fmaxf(x2.x + fmaf(v2.y, wv.x, bv.x), 0.f)
               + fmaxf(x3.x + fmaf(v3.y, wv.x, bv.x), 0.f);
        acc.y += fmaxf(x0.y + fmaf(v0.y, wv.y, bv.y), 0.f)
               + fmaxf(x1.y + fmaf(v1.y, wv.y, bv.y), 0.f)
               + fmaxf(x2.y + fmaf(v2.y, wv.y, bv.y), 0.f)
               + fmaxf(x3.y + fmaf(v3.y, wv.y, bv.y), 0.f);
        acc.z += fmaxf(x0.z + fmaf(v0.y, wv.z, bv.z), 0.f)
               + fmaxf(x1.z + fmaf(v1.y, wv.z, bv.z), 0.f)
               + fmaxf(x2.z + fmaf(v2.y, wv.z, bv.z), 0.f)
               + fmaxf(x3.z + fmaf(v3.y, wv.z, bv.z), 0.f);
        acc.w += fmaxf(x0.w + fmaf(v0.y, wv.w, bv.w), 0.f)
               + fmaxf(x1.w + fmaf(v1.y, wv.w, bv.w), 0.f)
               + fmaxf(x2.w + fmaf(v2.y, wv.w, bv.w), 0.f)
               + fmaxf(x3.w + fmaf(v3.y, wv.w, bv.w), 0.f);
    }
    for (; j < end; j++) {
        float2 v0 = g_sev[j];
        int s0 = __float_as_int(v0.x);
        float4 x0 = xv[(size_t)s0 * 32 + lane];
        acc.x += fmaxf(x0.x + fmaf(v0.y, wv.x, bv.x), 0.f);
        acc.y += fmaxf(x0.y + fmaf(v0.y, wv.y, bv.y), 0.f);
        acc.z += fmaxf(x0.z + fmaf(v0.y, wv.z, bv.z), 0.f);
        acc.w += fmaxf(x0.w + fmaf(v0.y, wv.w, bv.w), 0.f);
    }
    ((float4*)g_aggr)[(size_t)node * 32 + lane] = acc;
}

// ---------------- tensor-core GEMM: out = act(A @ W + bias), bf16x3 (R8-proven) ----------------
// block: 128 rows x 128 cols, 256 threads (8 warps), warp tile 32x64
// blockIdx.y selects weight half (+y*DIM*DIM) and output buffer (ioa/iob)
__global__ void __launch_bounds__(256, 2)
k_gemm_tc(int ia, const float* __restrict__ Wbase,
          const float* __restrict__ bias, int ioa, int iob,
          int relu, int nrows) {
    const float* W = Wbase + (size_t)blockIdx.y * DIM * DIM;
    int io = blockIdx.y ? iob : ioa;

    extern __shared__ uint32_t sWp[];          // 2 * 64 * BPITCH u32
    uint32_t* sHi = sWp;
    uint32_t* sLo = sWp + 64 * BPITCH;
    for (int i = threadIdx.x; i < 64 * 128; i += 256) {
        int k2 = i >> 7, n = i & 127;
        float v0 = __ldg(W + (2 * k2)     * DIM + n);
        float v1 = __ldg(W + (2 * k2 + 1) * DIM + n);
        uint32_t hi, lo;
        split2(make_float2(v0, v1), hi, lo);
        sHi[k2 * BPITCH + n] = hi;
        sLo[k2 * BPITCH + n] = lo;
    }
    __syncthreads();

    const float* A   = bufptr(ia);
    float*       out = bufptr(io);

    int warp = threadIdx.x >> 5, lane = threadIdx.x & 31;
    int g   = lane >> 2;    // 0..7
    int tid = lane & 3;     // 0..3
    int mbase = blockIdx.x * 128 + (warp >> 1) * 32;
    int nbase = (warp & 1) * 64;

    float acc[2][8][4];
    #pragma unroll
    for (int mt = 0; mt < 2; mt++)
        #pragma unroll
        for (int nt = 0; nt < 8; nt++)
            #pragma unroll
            for (int i = 0; i < 4; i++) acc[mt][nt][i] = 0.f;

    int r0[2], r1[2];
    #pragma unroll
    for (int mt = 0; mt < 2; mt++) {
        int a = mbase + mt * 16 + g;
        r0[mt] = min(a, nrows - 1);
        r1[mt] = min(a + 8, nrows - 1);
    }

    #pragma unroll 1
    for (int c0 = 0; c0 < 128; c0 += 16) {
        int kq = c0 + tid * 2;
        uint32_t ah[2][4], al[2][4];
        #pragma unroll
        for (int mt = 0; mt < 2; mt++) {
            float2 p00 = *(const float2*)(A + (size_t)r0[mt] * DIM + kq);
            float2 p10 = *(const float2*)(A + (size_t)r1[mt] * DIM + kq);
            float2 p01 = *(const float2*)(A + (size_t)r0[mt] * DIM + kq + 8);
            float2 p11 = *(const float2*)(A + (size_t)r1[mt] * DIM + kq + 8);
            split2(p00, ah[mt][0], al[mt][0]);
            split2(p10, ah[mt][1], al[mt][1]);
            split2(p01, ah[mt][2], al[mt][2]);
            split2(p11, ah[mt][3], al[mt][3]);
        }
        int kw = (c0 >> 1) + tid;   // word row in planes
        #pragma unroll
        for (int nh = 0; nh < 2; nh++) {
            uint32_t bh[4][2], bl[4][2];
            #pragma unroll
            for (int q = 0; q < 4; q++) {
                int col = nbase + (nh * 4 + q) * 8 + g;
                bh[q][0] = sHi[kw * BPITCH + col];
                bh[q][1] = sHi[(kw + 4) * BPITCH + col];
                bl[q][0] = sLo[kw * BPITCH + col];
                bl[q][1] = sLo[(kw + 4) * BPITCH + col];
            }
            #pragma unroll
            for (int mt = 0; mt < 2; mt++)
                #pragma unroll
                for (int q = 0; q < 4; q++) {
                    float* c = acc[mt][nh * 4 + q];
                    mma_bf16(c, al[mt], bh[q]);   // Al*Wh
                    mma_bf16(c, ah[mt], bl[q]);   // Ah*Wl
                    mma_bf16(c, ah[mt], bh[q]);   // Ah*Wh
                }
        }
    }

    #pragma unroll
    for (int mt = 0; mt < 2; mt++) {
        int ra = mbase + mt * 16 + g;
        int rb = ra + 8;
        #pragma unroll
        for (int nt = 0; nt < 8; nt++) {
            int c = nbase + nt * 8 + tid * 2;
            float b0 = bias ? __ldg(bias + c)     : 0.f;
            float b1 = bias ? __ldg(bias + c + 1) : 0.f;
            float v0 = acc[mt][nt][0] + b0, v1 = acc[mt][nt][1] + b1;
            float v2 = acc[mt][nt][2] + b0, v3 = acc[mt][nt][3] + b1;
            if (relu) {
                v0 = fmaxf(v0, 0.f); v1 = fmaxf(v1, 0.f);
                v2 = fmaxf(v2, 0.f); v3 = fmaxf(v3, 0.f);
            }
            if (ra < nrows) *(float2*)&out[(size_t)ra * DIM + c] = make_float2(v0, v1);
            if (rb < nrows) *(float2*)&out[(size_t)rb * DIM + c] = make_float2(v2, v3);
        }
    }
}

// ---------------- edge predictor, CSR order ----------------
__global__ void __launch_bounds__(256)
k_edge_pred_csr(const float* __restrict__ bp1,
                const float* __restrict__ Wp2,
                const float* __restrict__ bp2,
                float* __restrict__ out) {
    int gt   = blockIdx.x * blockDim.x + threadIdx.x;
    int node = gt >> 5;
    int lane = gt & 31;
    if (node >= N_NODES) return;

    float4 b1 = ((const float4*)bp1)[lane];
    float4 w2 = ((const float4*)Wp2)[lane];
    float  b2 = __ldg(bp2);

    float4 t = ((const float4*)(g_B + (size_t)node * DIM))[lane];
    t.x += b1.x; t.y += b1.y; t.z += b1.z; t.w += b1.w;

    const float4* av4 = (const float4*)g_h;
    int j   = g_row[node];
    int end = g_row[node + 1];

    for (; j + 1 < end; j += 2) {
        int2 p0i = g_sep[j], p1i = g_sep[j + 1];
        float4 a0 = av4[(size_t)p0i.x * 32 + lane];
        float4 a1 = av4[(size_t)p1i.x * 32 + lane];
        float p0 = 0.f, p1 = 0.f;
        p0 = fmaf(fmaxf(a0.x + t.x, 0.f), w2.x, p0);
        p0 = fmaf(fmaxf(a0.y + t.y, 0.f), w2.y, p0);
        p0 = fmaf(fmaxf(a0.z + t.z, 0.f), w2.z, p0);
        p0 = fmaf(fmaxf(a0.w + t.w, 0.f), w2.w, p0);
        p1 = fmaf(fmaxf(a1.x + t.x, 0.f), w2.x, p1);
        p1 = fmaf(fmaxf(a1.y + t.y, 0.f), w2.y, p1);
        p1 = fmaf(fmaxf(a1.z + t.z, 0.f), w2.z, p1);
        p1 = fmaf(fmaxf(a1.w + t.w, 0.f), w2.w, p1);
        #pragma unroll
        for (int o = 16; o > 0; o >>= 1) {
            p0 += __shfl_xor_sync(0xffffffffu, p0, o);
            p1 += __shfl_xor_sync(0xffffffffu, p1, o);
        }
        if (lane == 0) out[p0i.y] = p0 + b2;
        if (lane == 1) out[p1i.y] = p1 + b2;
    }
    if (j < end) {
        int2 p0i = g_sep[j];
        float4 a0 = av4[(size_t)p0i.x * 32 + lane];
        float p0 = 0.f;
        p0 = fmaf(fmaxf(a0.x + t.x, 0.f), w2.x, p0);
        p0 = fmaf(fmaxf(a0.y + t.y, 0.f), w2.y, p0);
        p0 = fmaf(fmaxf(a0.z + t.z, 0.f), w2.z, p0);
        p0 = fmaf(fmaxf(a0.w + t.w, 0.f), w2.w, p0);
        #pragma unroll
        for (int o = 16; o > 0; o >>= 1)
            p0 += __shfl_xor_sync(0xffffffffu, p0, o);
        if (lane == 0) out[p0i.y] = p0 + b2;
    }
}

// ---------------- launch ----------------
extern "C" void kernel_launch(void* const* d_in, const int* in_sizes, int n_in,
                              void* d_out, int out_size) {
    const float* x   = (const float*)d_in[0];
    const float* ea  = (const float*)d_in[1];
    const void*  ei  = d_in[2];
    const float* Wl1 = (const float*)d_in[3];
    const float* bl1 = (const float*)d_in[4];
    const float* Wl2 = (const float*)d_in[5];
    const float* bl2 = (const float*)d_in[6];
    const float* We  = (const float*)d_in[7];
    const float* be  = (const float*)d_in[8];
    const float* Wp1 = (const float*)d_in[9];
    const float* bp1 = (const float*)d_in[10];
    const float* Wp2 = (const float*)d_in[11];
    const float* bp2 = (const float*)d_in[12];
    float* out = (float*)d_out;

    const int GEMM_SMEM = 2 * 64 * BPITCH * (int)sizeof(uint32_t);  // 69632
    cudaFuncSetAttribute(k_gemm_tc, cudaFuncAttributeMaxDynamicSharedMemorySize,
                         GEMM_SMEM);

    const int GEMM_GRID = (N_NODES + 127) / 128;         // 391
    const int EDGE_GRID = (N_EDGES + 255) / 256;         // 3125
    const int NODE_GRID = (N_NODES + 255) / 256;         // 196
    const int AGGR_GRID = (N_NODES * 32 + 255) / 256;    // 6250

    dim3 gemm1(GEMM_GRID, 1, 1);
    dim3 gemm2(GEMM_GRID, 2, 1);

    // dtype detect + CSR build (once per call)
    k_detect_zero<<<NODE_GRID, 256>>>(ei);
    k_hist<<<EDGE_GRID, 256>>>(ei);
    k_scanA<<<SCAN_NB, 256>>>();
    k_scanB<<<1, 256>>>();
    k_scanC<<<SCAN_NB, 256>>>();
    k_scatter<<<EDGE_GRID, 256>>>(ei, ea);

    for (int l = 0; l < 3; l++) {
        // aggr = x + sum(msg);  layer 0 reads the external x directly
        k_aggr<<<AGGR_GRID, 256>>>((l == 0) ? x : nullptr,
                                   We + l * DIM, be + l * DIM);
        // h = relu(aggr @ Wl1 + bl1)
        k_gemm_tc<<<gemm1, 256, GEMM_SMEM>>>(2, Wl1 + l * DIM * DIM,
                                             bl1 + l * DIM, 1, 1, 1, N_NODES);
        // x = relu(h @ Wl2 + bl2)
        k_gemm_tc<<<gemm1, 256, GEMM_SMEM>>>(1, Wl2 + l * DIM * DIM,
                                             bl2 + l * DIM, 0, 0, 1, N_NODES);
    }

    // merged predictor GEMMs: y=0 -> A = x @ Wp1[0:128] (g_h),
    //                         y=1 -> B = x @ Wp1[128:256] (g_B)
    k_gemm_tc<<<gemm2, 256, GEMM_SMEM>>>(0, Wp1, nullptr, 1, 3, 0, N_NODES);

    k_edge_pred_csr<<<AGGR_GRID, 256>>>(bp1, Wp2, bp2, out);
}

// round 12
// speedup vs baseline: 1.2427x; 1.0155x over previous
#include <cuda_runtime.h>
#include <cstdint>

#define N_NODES 50000
#define N_EDGES 800000
#define DIM     128
#define SCAN_NB 196   // 196*256 = 50176 >= N_NODES
#define BPITCH  136   // u32 pitch for packed-bf16x2 W planes (conflict-free)

// ---------------- scratch (device globals; no allocation allowed) ----------------
__device__ float  g_xbuf[N_NODES * DIM];   // current node features
__device__ float  g_h   [N_NODES * DIM];   // hidden / predictor A
__device__ float  g_aggr[N_NODES * DIM];   // x + message aggregation / predictor B
__device__ float2 g_sev [N_EDGES];         // {src_bits, edge_attr} sorted by dst
__device__ int2   g_sep [N_EDGES];         // {src, edge_id} sorted by dst
__device__ int    g_rank[N_EDGES];         // arrival rank of edge within its dst
__device__ int    g_deg [N_NODES];
__device__ int    g_row [N_NODES + 1];
__device__ int    g_bsum[SCAN_NB];
__device__ int    g_is64;

__device__ __forceinline__ float* bufptr(int id) {
    switch (id) {
        case 0:  return g_xbuf;
        case 1:  return g_h;
        default: return g_aggr;
    }
}

// ---------------- bf16 / mma helpers ----------------
__device__ __forceinline__ uint32_t packbf(float vhi, float vlo) {
    uint32_t r;
    asm("cvt.rn.bf16x2.f32 %0, %1, %2;" : "=r"(r) : "f"(vhi), "f"(vlo));
    return r;
}
__device__ __forceinline__ void mma_bf16(float* c, const uint32_t* a,
                                         const uint32_t* b) {
    asm("mma.sync.aligned.m16n8k16.row.col.f32.bf16.bf16.f32 "
        "{%0,%1,%2,%3},{%4,%5,%6,%7},{%8,%9},{%0,%1,%2,%3};"
        : "+f"(c[0]), "+f"(c[1]), "+f"(c[2]), "+f"(c[3])
        : "r"(a[0]), "r"(a[1]), "r"(a[2]), "r"(a[3]), "r"(b[0]), "r"(b[1]));
}
// split (v.x = lower k, v.y = upper k) into bf16x2 hi + residual-lo words
__device__ __forceinline__ void split2(float2 v, uint32_t& hi, uint32_t& lo) {
    hi = packbf(v.y, v.x);
    float h0 = __uint_as_float(hi << 16);
    float h1 = __uint_as_float(hi & 0xffff0000u);
    lo = packbf(v.y - h1, v.x - h0);
}

// ---------------- edge-index access (dtype-agnostic) ----------------
__device__ __forceinline__ int ei_src(const void* ei, int e) {
    return g_is64 ? (int)((const long long*)ei)[e] : ((const int*)ei)[e];
}
__device__ __forceinline__ int ei_dst(const void* ei, int e) {
    return g_is64 ? (int)((const long long*)ei)[N_EDGES + e]
                  : ((const int*)ei)[N_EDGES + e];
}

// ---------------- dtype detect + degree zero (fused) ----------------
__global__ void k_detect_zero(const void* ei) {
    int i = blockIdx.x * blockDim.x + threadIdx.x;
    if (i < N_NODES) g_deg[i] = 0;
    if (blockIdx.x == 0) {
        __shared__ int s;
        if (threadIdx.x == 0) s = 0;
        __syncthreads();
        if (threadIdx.x < 64) {
            const unsigned* w = (const unsigned*)ei;
            if (w[2 * threadIdx.x + 1] != 0u) atomicOr(&s, 1);
        }
        __syncthreads();
        if (threadIdx.x == 0) g_is64 = (s == 0) ? 1 : 0;
    }
}

// ---------------- CSR build ----------------
// histogram + per-edge arrival rank (enables atomic-free scatter)
__global__ void k_hist(const void* ei) {
    int i = blockIdx.x * blockDim.x + threadIdx.x;
    if (i < N_EDGES) g_rank[i] = atomicAdd(&g_deg[ei_dst(ei, i)], 1);
}

__global__ void k_scanA() {
    __shared__ int s[256];
    int t = threadIdx.x;
    int idx = blockIdx.x * 256 + t;
    int v = (idx < N_NODES) ? g_deg[idx] : 0;
    s[t] = v;
    __syncthreads();
    #pragma unroll
    for (int off = 1; off < 256; off <<= 1) {
        int add = (t >= off) ? s[t - off] : 0;
        __syncthreads();
        s[t] += add;
        __syncthreads();
    }
    int incl = s[t];
    if (idx < N_NODES) g_row[idx] = incl - v;   // block-local exclusive
    if (t == 255) g_bsum[blockIdx.x] = incl;
}

// fused scanB+scanC: each block reduces bsum[0..blockIdx.x) and adds
__global__ void k_scanBC() {
    __shared__ int s[256];
    int t = threadIdx.x;
    s[t] = (t < SCAN_NB && t < blockIdx.x) ? g_bsum[t] : 0;
    __syncthreads();
    #pragma unroll
    for (int off = 128; off > 0; off >>= 1) {
        if (t < off) s[t] += s[t + off];
        __syncthreads();
    }
    int prefix = s[0];
    int idx = blockIdx.x * 256 + t;
    if (idx < N_NODES) g_row[idx] += prefix;
    if (idx == 0) g_row[N_NODES] = N_EDGES;
}

// atomic-free scatter: pos = row[dst] + rank
__global__ void k_scatter(const void* ei, const float* __restrict__ ea) {
    int e = blockIdx.x * blockDim.x + threadIdx.x;
    if (e >= N_EDGES) return;
    int d = ei_dst(ei, e);
    int s = ei_src(ei, e);
    int pos = g_row[d] + g_rank[e];
    g_sev[pos] = make_float2(__int_as_float(s), ea[e]);
    g_sep[pos] = make_int2(s, e);
}

// ---------------- CSR aggregation ----------------
// aggr[n] = x[n] + sum_{e in row n} relu(x[src_e] + a_e*We + be); warp per node
__global__ void __launch_bounds__(256)
k_aggr(const float* __restrict__ xext,
       const float* __restrict__ We, const float* __restrict__ be) {
    int gt   = blockIdx.x * blockDim.x + threadIdx.x;
    int node = gt >> 5;
    int lane = gt & 31;
    if (node >= N_NODES) return;

    const float* xin = xext ? xext : g_xbuf;

    float4 wv = ((const float4*)We)[lane];
    float4 bv = ((const float4*)be)[lane];
    const float4* xv = (const float4*)xin;

    float4 acc = xv[(size_t)node * 32 + lane];   // (1+eps)*x, eps=0
    int j   = g_row[node];
    int end = g_row[node + 1];

    for (; j + 3 < end; j += 4) {
        float2 v0 = g_sev[j],     v1 = g_sev[j + 1];
        float2 v2 = g_sev[j + 2], v3 = g_sev[j + 3];
        int s0 = __float_as_int(v0.x), s1 = __float_as_int(v1.x);
        int s2 = __float_as_int(v2.x), s3 = __float_as_int(v3.x);
        float4 x0 = xv[(size_t)s0 * 32 + lane];
        float4 x1 = xv[(size_t)s1 * 32 + lane];
        float4 x2 = xv[(size_t)s2 * 32 + lane];
        float4 x3 = xv[(size_t)s3 * 32 + lane];
        acc.x += fmaxf(x0.x + fmaf(v0.y, wv.x, bv.x), 0.f)
               + fmaxf(x1.x + fmaf(v1.y, wv.x, bv.x), 0.f)
               + fmaxf(x2.x + fmaf(v2.y, wv.x, bv.x), 0.f)
               + fmaxf(x3.x + fmaf(v3.y, wv.x, bv.x), 0.f);
        acc.y += fmaxf(x0.y + fmaf(v0.y, wv.y, bv.y), 0.f)
               + fmaxf(x1.y + fmaf(v1.y, wv.y, bv.y), 0.f)
               + fmaxf(x2.y + fmaf(v2.y, wv.y, bv.y), 0.f)
               + fmaxf(x3.y + fmaf(v3.y, wv.y, bv.y), 0.f);
        acc.z += fmaxf(x0.z + fmaf(v0.y, wv.z, bv.z), 0.f)
               + fmaxf(x1.z + fmaf(v1.y, wv.z, bv.z), 0.f)
               + fmaxf(x2.z + fmaf(v2.y, wv.z, bv.z), 0.f)
               + fmaxf(x3.z + fmaf(v3.y, wv.z, bv.z), 0.f);
        acc.w += fmaxf(x0.w + fmaf(v0.y, wv.w, bv.w), 0.f)
               + fmaxf(x1.w + fmaf(v1.y, wv.w, bv.w), 0.f)
               + fmaxf(x2.w + fmaf(v2.y, wv.w, bv.w), 0.f)
               + fmaxf(x3.w + fmaf(v3.y, wv.w, bv.w), 0.f);
    }
    for (; j < end; j++) {
        float2 v0 = g_sev[j];
        int s0 = __float_as_int(v0.x);
        float4 x0 = xv[(size_t)s0 * 32 + lane];
        acc.x += fmaxf(x0.x + fmaf(v0.y, wv.x, bv.x), 0.f);
        acc.y += fmaxf(x0.y + fmaf(v0.y, wv.y, bv.y), 0.f);
        acc.z += fmaxf(x0.z + fmaf(v0.y, wv.z, bv.z), 0.f);
        acc.w += fmaxf(x0.w + fmaf(v0.y, wv.w, bv.w), 0.f);
    }
    ((float4*)g_aggr)[(size_t)node * 32 + lane] = acc;
}

// ---------------- tensor-core GEMM: out = act(A @ W + bias), bf16x3 (R8-proven) ----------------
// block: 128 rows x 128 cols, 256 threads (8 warps), warp tile 32x64
// blockIdx.y selects weight half (+y*DIM*DIM) and output buffer (ioa/iob)
__global__ void __launch_bounds__(256, 2)
k_gemm_tc(int ia, const float* __restrict__ Wbase,
          const float* __restrict__ bias, int ioa, int iob,
          int relu, int nrows) {
    const float* W = Wbase + (size_t)blockIdx.y * DIM * DIM;
    int io = blockIdx.y ? iob : ioa;

    extern __shared__ uint32_t sWp[];          // 2 * 64 * BPITCH u32
    uint32_t* sHi = sWp;
    uint32_t* sLo = sWp + 64 * BPITCH;
    for (int i = threadIdx.x; i < 64 * 128; i += 256) {
        int k2 = i >> 7, n = i & 127;
        float v0 = __ldg(W + (2 * k2)     * DIM + n);
        float v1 = __ldg(W + (2 * k2 + 1) * DIM + n);
        uint32_t hi, lo;
        split2(make_float2(v0, v1), hi, lo);
        sHi[k2 * BPITCH + n] = hi;
        sLo[k2 * BPITCH + n] = lo;
    }
    __syncthreads();

    const float* A   = bufptr(ia);
    float*       out = bufptr(io);

    int warp = threadIdx.x >> 5, lane = threadIdx.x & 31;
    int g   = lane >> 2;    // 0..7
    int tid = lane & 3;     // 0..3
    int mbase = blockIdx.x * 128 + (warp >> 1) * 32;
    int nbase = (warp & 1) * 64;

    float acc[2][8][4];
    #pragma unroll
    for (int mt = 0; mt < 2; mt++)
        #pragma unroll
        for (int nt = 0; nt < 8; nt++)
            #pragma unroll
            for (int i = 0; i < 4; i++) acc[mt][nt][i] = 0.f;

    int r0[2], r1[2];
    #pragma unroll
    for (int mt = 0; mt < 2; mt++) {
        int a = mbase + mt * 16 + g;
        r0[mt] = min(a, nrows - 1);
        r1[mt] = min(a + 8, nrows - 1);
    }

    #pragma unroll 1
    for (int c0 = 0; c0 < 128; c0 += 16) {
        int kq = c0 + tid * 2;
        uint32_t ah[2][4], al[2][4];
        #pragma unroll
        for (int mt = 0; mt < 2; mt++) {
            float2 p00 = *(const float2*)(A + (size_t)r0[mt] * DIM + kq);
            float2 p10 = *(const float2*)(A + (size_t)r1[mt] * DIM + kq);
            float2 p01 = *(const float2*)(A + (size_t)r0[mt] * DIM + kq + 8);
            float2 p11 = *(const float2*)(A + (size_t)r1[mt] * DIM + kq + 8);
            split2(p00, ah[mt][0], al[mt][0]);
            split2(p10, ah[mt][1], al[mt][1]);
            split2(p01, ah[mt][2], al[mt][2]);
            split2(p11, ah[mt][3], al[mt][3]);
        }
        int kw = (c0 >> 1) + tid;   // word row in planes
        #pragma unroll
        for (int nh = 0; nh < 2; nh++) {
            uint32_t bh[4][2], bl[4][2];
            #pragma unroll
            for (int q = 0; q < 4; q++) {
                int col = nbase + (nh * 4 + q) * 8 + g;
                bh[q][0] = sHi[kw * BPITCH + col];
                bh[q][1] = sHi[(kw + 4) * BPITCH + col];
                bl[q][0] = sLo[kw * BPITCH + col];
                bl[q][1] = sLo[(kw + 4) * BPITCH + col];
            }
            #pragma unroll
            for (int mt = 0; mt < 2; mt++)
                #pragma unroll
                for (int q = 0; q < 4; q++) {
                    float* c = acc[mt][nh * 4 + q];
                    mma_bf16(c, al[mt], bh[q]);   // Al*Wh
                    mma_bf16(c, ah[mt], bl[q]);   // Ah*Wl
                    mma_bf16(c, ah[mt], bh[q]);   // Ah*Wh
                }
        }
    }

    #pragma unroll
    for (int mt = 0; mt < 2; mt++) {
        int ra = mbase + mt * 16 + g;
        int rb = ra + 8;
        #pragma unroll
        for (int nt = 0; nt < 8; nt++) {
            int c = nbase + nt * 8 + tid * 2;
            float b0 = bias ? __ldg(bias + c)     : 0.f;
            float b1 = bias ? __ldg(bias + c + 1) : 0.f;
            float v0 = acc[mt][nt][0] + b0, v1 = acc[mt][nt][1] + b1;
            float v2 = acc[mt][nt][2] + b0, v3 = acc[mt][nt][3] + b1;
            if (relu) {
                v0 = fmaxf(v0, 0.f); v1 = fmaxf(v1, 0.f);
                v2 = fmaxf(v2, 0.f); v3 = fmaxf(v3, 0.f);
            }
            if (ra < nrows) *(float2*)&out[(size_t)ra * DIM + c] = make_float2(v0, v1);
            if (rb < nrows) *(float2*)&out[(size_t)rb * DIM + c] = make_float2(v2, v3);
        }
    }
}

// ---------------- edge predictor, CSR order ----------------
// warp per node d: t = B[d] + bp1 (once); per edge gather A[src];
// p = relu(A[src]+t) . Wp2; shfl-reduce; out[eid] = p + bp2
__global__ void __launch_bounds__(256)
k_edge_pred_csr(const float* __restrict__ bp1,
                const float* __restrict__ Wp2,
                const float* __restrict__ bp2,
                float* __restrict__ out) {
    int gt   = blockIdx.x * blockDim.x + threadIdx.x;
    int node = gt >> 5;
    int lane = gt & 31;
    if (node >= N_NODES) return;

    float4 b1 = ((const float4*)bp1)[lane];
    float4 w2 = ((const float4*)Wp2)[lane];
    float  b2 = __ldg(bp2);

    float4 t = ((const float4*)(g_aggr + (size_t)node * DIM))[lane];  // B
    t.x += b1.x; t.y += b1.y; t.z += b1.z; t.w += b1.w;

    const float4* av4 = (const float4*)g_h;
    int j   = g_row[node];
    int end = g_row[node + 1];

    for (; j + 1 < end; j += 2) {
        int2 p0i = g_sep[j], p1i = g_sep[j + 1];
        float4 a0 = av4[(size_t)p0i.x * 32 + lane];
        float4 a1 = av4[(size_t)p1i.x * 32 + lane];
        float p0 = 0.f, p1 = 0.f;
        p0 = fmaf(fmaxf(a0.x + t.x, 0.f), w2.x, p0);
        p0 = fmaf(fmaxf(a0.y + t.y, 0.f), w2.y, p0);
        p0 = fmaf(fmaxf(a0.z + t.z, 0.f), w2.z, p0);
        p0 = fmaf(fmaxf(a0.w + t.w, 0.f), w2.w, p0);
        p1 = fmaf(fmaxf(a1.x + t.x, 0.f), w2.x, p1);
        p1 = fmaf(fmaxf(a1.y + t.y, 0.f), w2.y, p1);
        p1 = fmaf(fmaxf(a1.z + t.z, 0.f), w2.z, p1);
        p1 = fmaf(fmaxf(a1.w + t.w, 0.f), w2.w, p1);
        #pragma unroll
        for (int o = 16; o > 0; o >>= 1) {
            p0 += __shfl_xor_sync(0xffffffffu, p0, o);
            p1 += __shfl_xor_sync(0xffffffffu, p1, o);
        }
        if (lane == 0) out[p0i.y] = p0 + b2;
        if (lane == 1) out[p1i.y] = p1 + b2;
    }
    if (j < end) {
        int2 p0i = g_sep[j];
        float4 a0 = av4[(size_t)p0i.x * 32 + lane];
        float p0 = 0.f;
        p0 = fmaf(fmaxf(a0.x + t.x, 0.f), w2.x, p0);
        p0 = fmaf(fmaxf(a0.y + t.y, 0.f), w2.y, p0);
        p0 = fmaf(fmaxf(a0.z + t.z, 0.f), w2.z, p0);
        p0 = fmaf(fmaxf(a0.w + t.w, 0.f), w2.w, p0);
        #pragma unroll
        for (int o = 16; o > 0; o >>= 1)
            p0 += __shfl_xor_sync(0xffffffffu, p0, o);
        if (lane == 0) out[p0i.y] = p0 + b2;
    }
}

// ---------------- launch ----------------
extern "C" void kernel_launch(void* const* d_in, const int* in_sizes, int n_in,
                              void* d_out, int out_size) {
    const float* x   = (const float*)d_in[0];
    const float* ea  = (const float*)d_in[1];
    const void*  ei  = d_in[2];
    const float* Wl1 = (const float*)d_in[3];
    const float* bl1 = (const float*)d_in[4];
    const float* Wl2 = (const float*)d_in[5];
    const float* bl2 = (const float*)d_in[6];
    const float* We  = (const float*)d_in[7];
    const float* be  = (const float*)d_in[8];
    const float* Wp1 = (const float*)d_in[9];
    const float* bp1 = (const float*)d_in[10];
    const float* Wp2 = (const float*)d_in[11];
    const float* bp2 = (const float*)d_in[12];
    float* out = (float*)d_out;

    const int GEMM_SMEM = 2 * 64 * BPITCH * (int)sizeof(uint32_t);  // 69632
    cudaFuncSetAttribute(k_gemm_tc, cudaFuncAttributeMaxDynamicSharedMemorySize,
                         GEMM_SMEM);

    const int GEMM_GRID = (N_NODES + 127) / 128;         // 391
    const int EDGE_GRID = (N_EDGES + 255) / 256;         // 3125
    const int NODE_GRID = (N_NODES + 255) / 256;         // 196
    const int AGGR_GRID = (N_NODES * 32 + 255) / 256;    // 6250

    dim3 gemm1(GEMM_GRID, 1, 1);
    dim3 gemm2(GEMM_GRID, 2, 1);

    // dtype detect + CSR build (once per call)
    k_detect_zero<<<NODE_GRID, 256>>>(ei);
    k_hist<<<EDGE_GRID, 256>>>(ei);
    k_scanA<<<SCAN_NB, 256>>>();
    k_scanBC<<<SCAN_NB, 256>>>();
    k_scatter<<<EDGE_GRID, 256>>>(ei, ea);

    for (int l = 0; l < 3; l++) {
        // aggr = x + sum(msg);  layer 0 reads the external x directly
        k_aggr<<<AGGR_GRID, 256>>>((l == 0) ? x : nullptr,
                                   We + l * DIM, be + l * DIM);
        // h = relu(aggr @ Wl1 + bl1)
        k_gemm_tc<<<gemm1, 256, GEMM_SMEM>>>(2, Wl1 + l * DIM * DIM,
                                             bl1 + l * DIM, 1, 1, 1, N_NODES);
        // x = relu(h @ Wl2 + bl2)
        k_gemm_tc<<<gemm1, 256, GEMM_SMEM>>>(1, Wl2 + l * DIM * DIM,
                                             bl2 + l * DIM, 0, 0, 1, N_NODES);
    }

    // merged predictor GEMMs: y=0 -> A = x @ Wp1[0:128] (g_h),
    //                         y=1 -> B = x @ Wp1[128:256] (g_aggr, reused)
    k_gemm_tc<<<gemm2, 256, GEMM_SMEM>>>(0, Wp1, nullptr, 1, 2, 0, N_NODES);

    k_edge_pred_csr<<<AGGR_GRID, 256>>>(bp1, Wp2, bp2, out);
}